// round 14
// baseline (speedup 1.0000x reference)
#include <cuda_runtime.h>
#include <cstdint>

#define BATCH 8
#define NANCH 32768
#define NCLS  81
#define NC    80
#define TOPM  200
#define NMS_TH  0.45f
#define CONF_TH 0.01f
#define NCHUNK  7
#define NBIN    2048
#define ROWS    64
#define SPEC_BITS 0x3D8F5C29u   // __float_as_uint(0.07f)

__device__ float  g_scores[(size_t)BATCH * NC * NANCH];
__device__ float4 g_boxes [(size_t)BATCH * NANCH];
__device__ float  g_kept  [(size_t)BATCH * NC * TOPM];
__device__ float4 g_cand  [(size_t)BATCH * NC * TOPM];
__device__ unsigned long long g_cutoff[BATCH];

__device__ __forceinline__ int score_bin(float v) {
    int b = (int)(__float_as_uint(v) >> 15) - 30720;
    return min(max(b, 0), NBIN - 1);
}

// ===========================================================================
// Kernel 1: NO-MAX softmax + box decode. 64-row blocks, 4 threads/row.
// e = exp2(x*log2e) directly (logits ~N(0,1): range-safe, p invariant).
// ===========================================================================
__global__ void __launch_bounds__(256)
k_softmax_decode(const float* __restrict__ loc,
                 const float* __restrict__ conf,
                 const float* __restrict__ dbox)
{
    __shared__ float sm[ROWS * NCLS];    // 20736 B
    __shared__ float sinv[ROWS];

    const int blk = blockIdx.x;
    const int b   = blk / (NANCH / ROWS);
    const int n0  = (blk % (NANCH / ROWS)) * ROWS;
    const int tid = threadIdx.x;

    // stage 64 rows of conf (contiguous 20.25 KB): 1296 float4
    const float4* src4 = reinterpret_cast<const float4*>(
        conf + ((size_t)b * NANCH + n0) * NCLS);
    float4* sm4 = reinterpret_cast<float4*>(sm);
    #pragma unroll
    for (int it = 0; it < 6; it++) {
        int i = tid + it * 256;
        if (i < (ROWS * NCLS) / 4) sm4[i] = src4[i];
    }

    // box decode — threads 0..63
    if (tid < ROWS) {
        const int n = n0 + tid;
        float4 l = reinterpret_cast<const float4*>(loc)[(size_t)b * NANCH + n];
        float4 d = reinterpret_cast<const float4*>(dbox)[n];
        float cx = d.x + l.x * 0.1f * d.z;
        float cy = d.y + l.y * 0.1f * d.w;
        float w  = d.z * expf(l.z * 0.2f);
        float h  = d.w * expf(l.w * 0.2f);
        float x1 = cx - w * 0.5f;
        float y1 = cy - h * 0.5f;
        float4 o;
        o.x = fminf(fmaxf(x1, 0.f), 1.f);
        o.y = fminf(fmaxf(y1, 0.f), 1.f);
        o.z = fminf(fmaxf(x1 + w, 0.f), 1.f);
        o.w = fminf(fmaxf(y1 + h, 0.f), 1.f);
        g_boxes[(size_t)b * NANCH + n] = o;
    }
    __syncthreads();

    // no-max softmax: 4 threads/row; quarters 21/20/20/20 classes
    {
        const int r = tid >> 2;
        const int q = tid & 3;
        const int c0 = (q == 0) ? 0 : (1 + q * 20);
        const int cn = (q == 0) ? 21 : 20;
        float* row = sm + r * NCLS;

        const float L2E = 1.44269504088896340736f;
        float s = 0.f;
        #pragma unroll 7
        for (int c = 0; c < cn; c++) {
            float e = exp2f(row[c0 + c] * L2E);
            row[c0 + c] = e;
            s += e;
        }
        s += __shfl_xor_sync(0xFFFFFFFFu, s, 1);
        s += __shfl_xor_sync(0xFFFFFFFFu, s, 2);
        if (q == 0) sinv[r] = 1.0f / s;
    }
    __syncthreads();

    // transposed masked-score writes: 16 float4 per class (64 rows)
    #pragma unroll
    for (int it = 0; it < 5; it++) {
        int i = tid + it * 256;                  // i < 16*NC = 1280
        const int c   = i >> 4;                  // 0..79 (class c+1)
        const int rr4 = (i & 15) * 4;
        float4 p;
        float i0 = sinv[rr4], i1 = sinv[rr4+1], i2 = sinv[rr4+2], i3 = sinv[rr4+3];
        p.x = sm[(rr4    ) * NCLS + (c + 1)] * i0;
        p.y = sm[(rr4 + 1) * NCLS + (c + 1)] * i1;
        p.z = sm[(rr4 + 2) * NCLS + (c + 1)] * i2;
        p.w = sm[(rr4 + 3) * NCLS + (c + 1)] * i3;
        p.x = (p.x > CONF_TH) ? p.x : 0.f;
        p.y = (p.y > CONF_TH) ? p.y : 0.f;
        p.z = (p.z > CONF_TH) ? p.z : 0.f;
        p.w = (p.w > CONF_TH) ? p.w : 0.f;
        reinterpret_cast<float4*>(
            g_scores + ((size_t)b * NC + c) * NANCH + n0)[i & 15] = p;
    }
}

// ===========================================================================
// Kernel 2: speculative single-pass gather + exact fallback; bitonic + NMS.
// ===========================================================================
__global__ void __launch_bounds__(256)
k_topk_nms()
{
    __shared__ unsigned int hist[NBIN];
    __shared__ unsigned int psum[256];
    __shared__ unsigned long long buf[2048];
    __shared__ unsigned int s_cnt;
    __shared__ int s_bin, s_g, s_P;
    __shared__ float4 s_bx[TOPM];
    __shared__ float  s_area[TOPM];
    __shared__ float  s_sc[TOPM];
    __shared__ unsigned int s_sup[TOPM * NCHUNK];
    __shared__ unsigned int s_act[NCHUNK];
    __shared__ int s_keep[TOPM];

    const int bc  = blockIdx.x;
    const int b   = bc / NC;
    const int tid = threadIdx.x;
    const float4* d4 = reinterpret_cast<const float4*>(g_scores + (size_t)bc * NANCH);

    if (tid == 0) s_cnt = 0;
    __syncthreads();

    for (int i = tid; i < NANCH / 4; i += 256) {
        float4 v = d4[i];
        const float vs[4] = {v.x, v.y, v.z, v.w};
        #pragma unroll
        for (int j = 0; j < 4; j++) {
            unsigned int u = __float_as_uint(vs[j]);
            if (u >= SPEC_BITS) {
                unsigned int pos = atomicAdd(&s_cnt, 1u);
                if (pos < 2048) {
                    unsigned int idx = 4 * i + j;
                    buf[pos] = ((unsigned long long)u << 32) |
                               (unsigned long long)(0xFFFFFFFFu - idx);
                }
            }
        }
    }
    __syncthreads();
    int cnt = (int)s_cnt;
    __syncthreads();

    if (cnt < TOPM || cnt > 2048) {
        for (int i = tid; i < NBIN; i += 256) hist[i] = 0;
        if (tid == 0) s_cnt = 0;
        __syncthreads();
        for (int i = tid; i < NANCH / 4; i += 256) {
            float4 v = d4[i];
            if (v.x > CONF_TH) atomicAdd(&hist[score_bin(v.x)], 1u);
            if (v.y > CONF_TH) atomicAdd(&hist[score_bin(v.y)], 1u);
            if (v.z > CONF_TH) atomicAdd(&hist[score_bin(v.z)], 1u);
            if (v.w > CONF_TH) atomicAdd(&hist[score_bin(v.w)], 1u);
        }
        __syncthreads();
        { unsigned int s = 0;
          #pragma unroll
          for (int j = 0; j < 8; j++) s += hist[tid * 8 + j];
          psum[tid] = s; }
        __syncthreads();
        if (tid == 0) {
            int acc = 0, binq = -1;
            for (int t = 255; t >= 0; t--) {
                if (acc + (int)psum[t] >= TOPM) {
                    for (int bb = t * 8 + 7; bb >= t * 8; bb--) {
                        int c2 = (int)hist[bb];
                        if (acc + c2 >= TOPM) { binq = bb; break; }
                        acc += c2;
                    }
                    break;
                }
                acc += (int)psum[t];
            }
            s_bin = binq;
        }
        __syncthreads();
        const int binq = s_bin;
        const unsigned int thr = (binq < 0) ? 0u
                               : ((unsigned int)(binq + 30720) << 15);
        for (int i = tid; i < NANCH / 4; i += 256) {
            float4 v = d4[i];
            const float vs[4] = {v.x, v.y, v.z, v.w};
            #pragma unroll
            for (int j = 0; j < 4; j++) {
                float val = vs[j];
                unsigned int u = __float_as_uint(val);
                if (val > 0.f && u >= thr) {
                    unsigned int pos = atomicAdd(&s_cnt, 1u);
                    if (pos < 2048) {
                        unsigned int idx = 4 * i + j;
                        buf[pos] = ((unsigned long long)u << 32) |
                                   (unsigned long long)(0xFFFFFFFFu - idx);
                    }
                }
            }
        }
        __syncthreads();
        cnt = (int)s_cnt;
        __syncthreads();
    }

    if (tid == 0) {
        int g = min(cnt, 2048);
        int P = 256;
        while (P < g) P <<= 1;
        s_g = g; s_P = P;
    }
    __syncthreads();
    const int g = s_g, P = s_P;
    for (int i = tid; i < P; i += 256) if (i >= g) buf[i] = 0ull;
    __syncthreads();

    for (int k = 2; k <= P; k <<= 1) {
        for (int j = k >> 1; j > 0; j >>= 1) {
            for (int t = tid; t < P; t += 256) {
                int ixj = t ^ j;
                if (ixj > t) {
                    unsigned long long a = buf[t], c2 = buf[ixj];
                    bool dirDesc = ((t & k) == 0);
                    if ((a < c2) == dirDesc) { buf[t] = c2; buf[ixj] = a; }
                }
            }
            __syncthreads();
        }
    }

    bool val_f = false;
    if (tid < TOPM) {
        float sc; float4 bx;
        if (tid < g) {
            unsigned long long cmp = buf[tid];
            sc = __uint_as_float((unsigned int)(cmp >> 32));
            unsigned int idx = 0xFFFFFFFFu - (unsigned int)(cmp & 0xFFFFFFFFull);
            bx = g_boxes[(size_t)b * NANCH + idx];
            val_f = true;
        } else {
            sc = 0.f; bx = make_float4(0.f, 0.f, 0.f, 0.f);
        }
        s_sc[tid]   = sc;
        s_bx[tid]   = bx;
        s_area[tid] = (bx.z - bx.x) * (bx.w - bx.y);
        s_keep[tid] = 0;
    }
    {
        unsigned int bm = __ballot_sync(0xFFFFFFFFu, val_f);
        if ((tid & 31) == 0 && (tid >> 5) < NCHUNK) s_act[tid >> 5] = bm;
    }
    __syncthreads();

    for (int task = tid; task < TOPM * NCHUNK; task += 256) {
        const int i     = task / NCHUNK;
        const int chunk = task % NCHUNK;
        const float4 bi = s_bx[i];
        const float  ai = s_area[i];
        unsigned int bits = 0;
        const int jmax = min(32, TOPM - chunk * 32);
        #pragma unroll 4
        for (int bb = 0; bb < jmax; bb++) {
            const int j = chunk * 32 + bb;
            float4 bj = s_bx[j];
            float xx1 = fmaxf(bi.x, bj.x);
            float yy1 = fmaxf(bi.y, bj.y);
            float xx2 = fminf(bi.z, bj.z);
            float yy2 = fminf(bi.w, bj.w);
            float inter = fmaxf(xx2 - xx1, 0.f) * fmaxf(yy2 - yy1, 0.f);
            float uni   = s_area[j] - inter + ai;
            float iou   = inter / uni;
            if (!(iou <= NMS_TH)) bits |= (1u << bb);
        }
        s_sup[task] = bits;
    }
    __syncthreads();

    if (tid < 32) {
        unsigned int act = (tid < NCHUNK) ? s_act[tid] : 0u;
        for (int i = 0; i < TOPM; i++) {
            unsigned int owner_act = __shfl_sync(0xFFFFFFFFu, act, i >> 5);
            bool k = (owner_act >> (i & 31)) & 1u;
            if (k) {
                if (tid < NCHUNK) act &= ~s_sup[i * NCHUNK + tid];
                if (tid == 0) s_keep[i] = 1;
            }
        }
    }
    __syncthreads();

    if (tid < TOPM) {
        g_kept[(size_t)bc * TOPM + tid] = s_keep[tid] ? s_sc[tid] : 0.f;
        g_cand[(size_t)bc * TOPM + tid] = s_bx[tid];
    }
}

// ===========================================================================
// Kernel 3: per-batch global top-200 composite cutoff (unchanged).
// ===========================================================================
__global__ void __launch_bounds__(256)
k_global_cutoff()
{
    __shared__ unsigned int hist[NBIN];
    __shared__ unsigned int psum[256];
    __shared__ unsigned long long buf[2048];
    __shared__ unsigned int s_cnt;
    __shared__ int s_bin, s_g, s_P;

    const int b   = blockIdx.x;
    const int tid = threadIdx.x;
    const int NTOT = NC * TOPM;
    const float* data = g_kept + (size_t)b * NTOT;
    const float4* d4  = reinterpret_cast<const float4*>(data);

    for (int i = tid; i < NBIN; i += 256) hist[i] = 0;
    __syncthreads();
    for (int i = tid; i < NTOT / 4; i += 256) {
        float4 v = d4[i];
        if (v.x > 0.f) atomicAdd(&hist[score_bin(v.x)], 1u);
        if (v.y > 0.f) atomicAdd(&hist[score_bin(v.y)], 1u);
        if (v.z > 0.f) atomicAdd(&hist[score_bin(v.z)], 1u);
        if (v.w > 0.f) atomicAdd(&hist[score_bin(v.w)], 1u);
    }
    __syncthreads();
    { unsigned int s = 0;
      #pragma unroll
      for (int j = 0; j < 8; j++) s += hist[tid * 8 + j];
      psum[tid] = s; }
    __syncthreads();
    if (tid == 0) {
        int acc = 0, binq = -1;
        for (int t = 255; t >= 0; t--) {
            if (acc + (int)psum[t] >= TOPM) {
                for (int bb = t * 8 + 7; bb >= t * 8; bb--) {
                    int cnt = (int)hist[bb];
                    if (acc + cnt >= TOPM) { binq = bb; break; }
                    acc += cnt;
                }
                break;
            }
            acc += (int)psum[t];
        }
        s_bin = binq;
        s_cnt = 0;
    }
    __syncthreads();
    const int binq = s_bin;

    if (binq < 0) {
        if (tid == 0) g_cutoff[b] = 0ull;
        return;
    }
    const unsigned int thr = (unsigned int)(binq + 30720) << 15;

    for (int i = tid; i < NTOT / 4; i += 256) {
        float4 v = d4[i];
        const float vs[4] = {v.x, v.y, v.z, v.w};
        #pragma unroll
        for (int j = 0; j < 4; j++) {
            float val = vs[j];
            unsigned int u = __float_as_uint(val);
            if (val > 0.f && u >= thr) {
                unsigned int p = atomicAdd(&s_cnt, 1u);
                if (p < 2048) {
                    unsigned int idx = 4 * i + j;
                    buf[p] = ((unsigned long long)u << 32) |
                             (unsigned long long)(0xFFFFFFFFu - idx);
                }
            }
        }
    }
    __syncthreads();
    if (tid == 0) {
        int g = (int)min(s_cnt, 2048u);
        int P = 256;
        while (P < g) P <<= 1;
        s_g = g; s_P = P;
    }
    __syncthreads();
    const int g = s_g, P = s_P;
    for (int i = tid; i < P; i += 256) if (i >= g) buf[i] = 0ull;
    __syncthreads();

    for (int k = 2; k <= P; k <<= 1) {
        for (int j = k >> 1; j > 0; j >>= 1) {
            for (int t = tid; t < P; t += 256) {
                int ixj = t ^ j;
                if (ixj > t) {
                    unsigned long long a = buf[t], c2 = buf[ixj];
                    bool dirDesc = ((t & k) == 0);
                    if ((a < c2) == dirDesc) { buf[t] = c2; buf[ixj] = a; }
                }
            }
            __syncthreads();
        }
    }

    if (tid == 0)
        g_cutoff[b] = buf[TOPM - 1];
}

// ===========================================================================
// Kernel 4: output writer (unchanged).
// ===========================================================================
__global__ void __launch_bounds__(256)
k_write(float* __restrict__ out)
{
    __shared__ unsigned int wcnt[8];
    const int c   = blockIdx.x;
    const int b   = blockIdx.y;
    const int tid = threadIdx.x;

    float* o = out + ((size_t)(b * NCLS + c)) * TOPM * 5;
    for (int i = tid; i < TOPM * 5; i += 256) o[i] = 0.f;
    if (c == 0) return;
    __syncthreads();

    const int c80 = c - 1;
    const size_t base = ((size_t)b * NC + c80) * TOPM;
    const unsigned long long cut = g_cutoff[b];

    float v = 0.f; bool flag = false; float4 bx = make_float4(0.f, 0.f, 0.f, 0.f);
    if (tid < TOPM) {
        v = g_kept[base + tid];
        if (v > 0.f) {
            unsigned long long comp =
                ((unsigned long long)__float_as_uint(v) << 32) |
                (unsigned long long)(0xFFFFFFFFu - (unsigned int)(c80 * TOPM + tid));
            flag = (comp >= cut);
        }
        if (flag) bx = g_cand[base + tid];
    }
    unsigned int ball = __ballot_sync(0xFFFFFFFFu, flag);
    const int wid = tid >> 5, lane = tid & 31;
    if (lane == 0) wcnt[wid] = __popc(ball);
    __syncthreads();
    int off = 0;
    for (int w = 0; w < wid; w++) off += (int)wcnt[w];
    if (flag) {
        int pos = off + __popc(ball & ((1u << lane) - 1));
        float* p = o + (size_t)pos * 5;
        p[0] = v; p[1] = bx.x; p[2] = bx.y; p[3] = bx.z; p[4] = bx.w;
    }
}

// ===========================================================================
extern "C" void kernel_launch(void* const* d_in, const int* in_sizes, int n_in,
                              void* d_out, int out_size)
{
    const float* loc  = (const float*)d_in[0];
    const float* conf = (const float*)d_in[1];
    const float* dbox = (const float*)d_in[2];
    float* out = (float*)d_out;

    k_softmax_decode<<<BATCH * (NANCH / ROWS), 256>>>(loc, conf, dbox);
    k_topk_nms<<<BATCH * NC, 256>>>();
    k_global_cutoff<<<BATCH, 256>>>();
    k_write<<<dim3(NCLS, BATCH), 256>>>(out);
}

// round 15
// speedup vs baseline: 1.5974x; 1.5974x over previous
#include <cuda_runtime.h>
#include <cstdint>

#define BATCH 8
#define NANCH 32768
#define NCLS  81
#define NC    80
#define TOPM  200
#define NMS_TH  0.45f
#define CONF_TH 0.01f
#define NCHUNK  7
#define NBIN    2048
#define ROWS    64
#define SPEC_BITS 0x3D8F5C29u   // __float_as_uint(0.07f)

__device__ float  g_scores[(size_t)BATCH * NC * NANCH];
__device__ float4 g_boxes [(size_t)BATCH * NANCH];
__device__ float  g_kept  [(size_t)BATCH * NC * TOPM];
__device__ float4 g_cand  [(size_t)BATCH * NC * TOPM];
__device__ unsigned long long g_cutoff[BATCH];

__device__ __forceinline__ int score_bin(float v) {
    int b = (int)(__float_as_uint(v) >> 15) - 30720;
    return min(max(b, 0), NBIN - 1);
}

// ===========================================================================
// Kernel 1: NO-MAX softmax + box decode. 64-row blocks, 4 threads/row.
// e = exp2(x*log2e) directly (logits ~N(0,1): range-safe, p invariant).
// ===========================================================================
__global__ void __launch_bounds__(256)
k_softmax_decode(const float* __restrict__ loc,
                 const float* __restrict__ conf,
                 const float* __restrict__ dbox)
{
    __shared__ float sm[ROWS * NCLS];    // 20736 B
    __shared__ float sinv[ROWS];

    const int blk = blockIdx.x;
    const int b   = blk / (NANCH / ROWS);
    const int n0  = (blk % (NANCH / ROWS)) * ROWS;
    const int tid = threadIdx.x;

    // stage 64 rows of conf (contiguous 20.25 KB): 1296 float4
    const float4* src4 = reinterpret_cast<const float4*>(
        conf + ((size_t)b * NANCH + n0) * NCLS);
    float4* sm4 = reinterpret_cast<float4*>(sm);
    #pragma unroll
    for (int it = 0; it < 6; it++) {
        int i = tid + it * 256;
        if (i < (ROWS * NCLS) / 4) sm4[i] = src4[i];
    }

    // box decode — threads 0..63
    if (tid < ROWS) {
        const int n = n0 + tid;
        float4 l = reinterpret_cast<const float4*>(loc)[(size_t)b * NANCH + n];
        float4 d = reinterpret_cast<const float4*>(dbox)[n];
        float cx = d.x + l.x * 0.1f * d.z;
        float cy = d.y + l.y * 0.1f * d.w;
        float w  = d.z * expf(l.z * 0.2f);
        float h  = d.w * expf(l.w * 0.2f);
        float x1 = cx - w * 0.5f;
        float y1 = cy - h * 0.5f;
        float4 o;
        o.x = fminf(fmaxf(x1, 0.f), 1.f);
        o.y = fminf(fmaxf(y1, 0.f), 1.f);
        o.z = fminf(fmaxf(x1 + w, 0.f), 1.f);
        o.w = fminf(fmaxf(y1 + h, 0.f), 1.f);
        g_boxes[(size_t)b * NANCH + n] = o;
    }
    __syncthreads();

    // no-max softmax: 4 threads/row; quarters 21/20/20/20 classes
    {
        const int r = tid >> 2;
        const int q = tid & 3;
        const int c0 = (q == 0) ? 0 : (1 + q * 20);
        const int cn = (q == 0) ? 21 : 20;
        float* row = sm + r * NCLS;

        const float L2E = 1.44269504088896340736f;
        float s = 0.f;
        #pragma unroll 7
        for (int c = 0; c < cn; c++) {
            float e = exp2f(row[c0 + c] * L2E);
            row[c0 + c] = e;
            s += e;
        }
        s += __shfl_xor_sync(0xFFFFFFFFu, s, 1);
        s += __shfl_xor_sync(0xFFFFFFFFu, s, 2);
        if (q == 0) sinv[r] = 1.0f / s;
    }
    __syncthreads();

    // transposed masked-score writes: 16 float4 per class (64 rows)
    #pragma unroll
    for (int it = 0; it < 5; it++) {
        int i = tid + it * 256;                  // i < 16*NC = 1280
        const int c   = i >> 4;                  // 0..79 (class c+1)
        const int rr4 = (i & 15) * 4;
        float4 p;
        float i0 = sinv[rr4], i1 = sinv[rr4+1], i2 = sinv[rr4+2], i3 = sinv[rr4+3];
        p.x = sm[(rr4    ) * NCLS + (c + 1)] * i0;
        p.y = sm[(rr4 + 1) * NCLS + (c + 1)] * i1;
        p.z = sm[(rr4 + 2) * NCLS + (c + 1)] * i2;
        p.w = sm[(rr4 + 3) * NCLS + (c + 1)] * i3;
        p.x = (p.x > CONF_TH) ? p.x : 0.f;
        p.y = (p.y > CONF_TH) ? p.y : 0.f;
        p.z = (p.z > CONF_TH) ? p.z : 0.f;
        p.w = (p.w > CONF_TH) ? p.w : 0.f;
        reinterpret_cast<float4*>(
            g_scores + ((size_t)b * NC + c) * NANCH + n0)[i & 15] = p;
    }
}

// ===========================================================================
// Kernel 2: speculative single-pass gather + exact fallback; bitonic + NMS.
// ===========================================================================
__global__ void __launch_bounds__(256)
k_topk_nms()
{
    __shared__ unsigned int hist[NBIN];
    __shared__ unsigned int psum[256];
    __shared__ unsigned long long buf[2048];
    __shared__ unsigned int s_cnt;
    __shared__ int s_bin, s_g, s_P;
    __shared__ float4 s_bx[TOPM];
    __shared__ float  s_area[TOPM];
    __shared__ float  s_sc[TOPM];
    __shared__ unsigned int s_sup[TOPM * NCHUNK];
    __shared__ unsigned int s_act[NCHUNK];
    __shared__ int s_keep[TOPM];

    const int bc  = blockIdx.x;
    const int b   = bc / NC;
    const int tid = threadIdx.x;
    const float4* d4 = reinterpret_cast<const float4*>(g_scores + (size_t)bc * NANCH);

    if (tid == 0) s_cnt = 0;
    __syncthreads();

    for (int i = tid; i < NANCH / 4; i += 256) {
        float4 v = d4[i];
        const float vs[4] = {v.x, v.y, v.z, v.w};
        #pragma unroll
        for (int j = 0; j < 4; j++) {
            unsigned int u = __float_as_uint(vs[j]);
            if (u >= SPEC_BITS) {
                unsigned int pos = atomicAdd(&s_cnt, 1u);
                if (pos < 2048) {
                    unsigned int idx = 4 * i + j;
                    buf[pos] = ((unsigned long long)u << 32) |
                               (unsigned long long)(0xFFFFFFFFu - idx);
                }
            }
        }
    }
    __syncthreads();
    int cnt = (int)s_cnt;
    __syncthreads();

    if (cnt < TOPM || cnt > 2048) {
        for (int i = tid; i < NBIN; i += 256) hist[i] = 0;
        if (tid == 0) s_cnt = 0;
        __syncthreads();
        for (int i = tid; i < NANCH / 4; i += 256) {
            float4 v = d4[i];
            if (v.x > CONF_TH) atomicAdd(&hist[score_bin(v.x)], 1u);
            if (v.y > CONF_TH) atomicAdd(&hist[score_bin(v.y)], 1u);
            if (v.z > CONF_TH) atomicAdd(&hist[score_bin(v.z)], 1u);
            if (v.w > CONF_TH) atomicAdd(&hist[score_bin(v.w)], 1u);
        }
        __syncthreads();
        { unsigned int s = 0;
          #pragma unroll
          for (int j = 0; j < 8; j++) s += hist[tid * 8 + j];
          psum[tid] = s; }
        __syncthreads();
        if (tid == 0) {
            int acc = 0, binq = -1;
            for (int t = 255; t >= 0; t--) {
                if (acc + (int)psum[t] >= TOPM) {
                    for (int bb = t * 8 + 7; bb >= t * 8; bb--) {
                        int c2 = (int)hist[bb];
                        if (acc + c2 >= TOPM) { binq = bb; break; }
                        acc += c2;
                    }
                    break;
                }
                acc += (int)psum[t];
            }
            s_bin = binq;
        }
        __syncthreads();
        const int binq = s_bin;
        const unsigned int thr = (binq < 0) ? 0u
                               : ((unsigned int)(binq + 30720) << 15);
        for (int i = tid; i < NANCH / 4; i += 256) {
            float4 v = d4[i];
            const float vs[4] = {v.x, v.y, v.z, v.w};
            #pragma unroll
            for (int j = 0; j < 4; j++) {
                float val = vs[j];
                unsigned int u = __float_as_uint(val);
                if (val > 0.f && u >= thr) {
                    unsigned int pos = atomicAdd(&s_cnt, 1u);
                    if (pos < 2048) {
                        unsigned int idx = 4 * i + j;
                        buf[pos] = ((unsigned long long)u << 32) |
                                   (unsigned long long)(0xFFFFFFFFu - idx);
                    }
                }
            }
        }
        __syncthreads();
        cnt = (int)s_cnt;
        __syncthreads();
    }

    if (tid == 0) {
        int g = min(cnt, 2048);
        int P = 256;
        while (P < g) P <<= 1;
        s_g = g; s_P = P;
    }
    __syncthreads();
    const int g = s_g, P = s_P;
    for (int i = tid; i < P; i += 256) if (i >= g) buf[i] = 0ull;
    __syncthreads();

    for (int k = 2; k <= P; k <<= 1) {
        for (int j = k >> 1; j > 0; j >>= 1) {
            for (int t = tid; t < P; t += 256) {
                int ixj = t ^ j;
                if (ixj > t) {
                    unsigned long long a = buf[t], c2 = buf[ixj];
                    bool dirDesc = ((t & k) == 0);
                    if ((a < c2) == dirDesc) { buf[t] = c2; buf[ixj] = a; }
                }
            }
            __syncthreads();
        }
    }

    bool val_f = false;
    if (tid < TOPM) {
        float sc; float4 bx;
        if (tid < g) {
            unsigned long long cmp = buf[tid];
            sc = __uint_as_float((unsigned int)(cmp >> 32));
            unsigned int idx = 0xFFFFFFFFu - (unsigned int)(cmp & 0xFFFFFFFFull);
            bx = g_boxes[(size_t)b * NANCH + idx];
            val_f = true;
        } else {
            sc = 0.f; bx = make_float4(0.f, 0.f, 0.f, 0.f);
        }
        s_sc[tid]   = sc;
        s_bx[tid]   = bx;
        s_area[tid] = (bx.z - bx.x) * (bx.w - bx.y);
        s_keep[tid] = 0;
    }
    {
        unsigned int bm = __ballot_sync(0xFFFFFFFFu, val_f);
        if ((tid & 31) == 0 && (tid >> 5) < NCHUNK) s_act[tid >> 5] = bm;
    }
    __syncthreads();

    for (int task = tid; task < TOPM * NCHUNK; task += 256) {
        const int i     = task / NCHUNK;
        const int chunk = task % NCHUNK;
        const float4 bi = s_bx[i];
        const float  ai = s_area[i];
        unsigned int bits = 0;
        const int jmax = min(32, TOPM - chunk * 32);
        #pragma unroll 4
        for (int bb = 0; bb < jmax; bb++) {
            const int j = chunk * 32 + bb;
            float4 bj = s_bx[j];
            float xx1 = fmaxf(bi.x, bj.x);
            float yy1 = fmaxf(bi.y, bj.y);
            float xx2 = fminf(bi.z, bj.z);
            float yy2 = fminf(bi.w, bj.w);
            float inter = fmaxf(xx2 - xx1, 0.f) * fmaxf(yy2 - yy1, 0.f);
            float uni   = s_area[j] - inter + ai;
            float iou   = inter / uni;
            if (!(iou <= NMS_TH)) bits |= (1u << bb);
        }
        s_sup[task] = bits;
    }
    __syncthreads();

    if (tid < 32) {
        unsigned int act = (tid < NCHUNK) ? s_act[tid] : 0u;
        for (int i = 0; i < TOPM; i++) {
            unsigned int owner_act = __shfl_sync(0xFFFFFFFFu, act, i >> 5);
            bool k = (owner_act >> (i & 31)) & 1u;
            if (k) {
                if (tid < NCHUNK) act &= ~s_sup[i * NCHUNK + tid];
                if (tid == 0) s_keep[i] = 1;
            }
        }
    }
    __syncthreads();

    if (tid < TOPM) {
        g_kept[(size_t)bc * TOPM + tid] = s_keep[tid] ? s_sc[tid] : 0.f;
        g_cand[(size_t)bc * TOPM + tid] = s_bx[tid];
    }
}

// ===========================================================================
// Kernel 3: per-batch global top-200 composite cutoff (unchanged).
// ===========================================================================
__global__ void __launch_bounds__(256)
k_global_cutoff()
{
    __shared__ unsigned int hist[NBIN];
    __shared__ unsigned int psum[256];
    __shared__ unsigned long long buf[2048];
    __shared__ unsigned int s_cnt;
    __shared__ int s_bin, s_g, s_P;

    const int b   = blockIdx.x;
    const int tid = threadIdx.x;
    const int NTOT = NC * TOPM;
    const float* data = g_kept + (size_t)b * NTOT;
    const float4* d4  = reinterpret_cast<const float4*>(data);

    for (int i = tid; i < NBIN; i += 256) hist[i] = 0;
    __syncthreads();
    for (int i = tid; i < NTOT / 4; i += 256) {
        float4 v = d4[i];
        if (v.x > 0.f) atomicAdd(&hist[score_bin(v.x)], 1u);
        if (v.y > 0.f) atomicAdd(&hist[score_bin(v.y)], 1u);
        if (v.z > 0.f) atomicAdd(&hist[score_bin(v.z)], 1u);
        if (v.w > 0.f) atomicAdd(&hist[score_bin(v.w)], 1u);
    }
    __syncthreads();
    { unsigned int s = 0;
      #pragma unroll
      for (int j = 0; j < 8; j++) s += hist[tid * 8 + j];
      psum[tid] = s; }
    __syncthreads();
    if (tid == 0) {
        int acc = 0, binq = -1;
        for (int t = 255; t >= 0; t--) {
            if (acc + (int)psum[t] >= TOPM) {
                for (int bb = t * 8 + 7; bb >= t * 8; bb--) {
                    int cnt = (int)hist[bb];
                    if (acc + cnt >= TOPM) { binq = bb; break; }
                    acc += cnt;
                }
                break;
            }
            acc += (int)psum[t];
        }
        s_bin = binq;
        s_cnt = 0;
    }
    __syncthreads();
    const int binq = s_bin;

    if (binq < 0) {
        if (tid == 0) g_cutoff[b] = 0ull;
        return;
    }
    const unsigned int thr = (unsigned int)(binq + 30720) << 15;

    for (int i = tid; i < NTOT / 4; i += 256) {
        float4 v = d4[i];
        const float vs[4] = {v.x, v.y, v.z, v.w};
        #pragma unroll
        for (int j = 0; j < 4; j++) {
            float val = vs[j];
            unsigned int u = __float_as_uint(val);
            if (val > 0.f && u >= thr) {
                unsigned int p = atomicAdd(&s_cnt, 1u);
                if (p < 2048) {
                    unsigned int idx = 4 * i + j;
                    buf[p] = ((unsigned long long)u << 32) |
                             (unsigned long long)(0xFFFFFFFFu - idx);
                }
            }
        }
    }
    __syncthreads();
    if (tid == 0) {
        int g = (int)min(s_cnt, 2048u);
        int P = 256;
        while (P < g) P <<= 1;
        s_g = g; s_P = P;
    }
    __syncthreads();
    const int g = s_g, P = s_P;
    for (int i = tid; i < P; i += 256) if (i >= g) buf[i] = 0ull;
    __syncthreads();

    for (int k = 2; k <= P; k <<= 1) {
        for (int j = k >> 1; j > 0; j >>= 1) {
            for (int t = tid; t < P; t += 256) {
                int ixj = t ^ j;
                if (ixj > t) {
                    unsigned long long a = buf[t], c2 = buf[ixj];
                    bool dirDesc = ((t & k) == 0);
                    if ((a < c2) == dirDesc) { buf[t] = c2; buf[ixj] = a; }
                }
            }
            __syncthreads();
        }
    }

    if (tid == 0)
        g_cutoff[b] = buf[TOPM - 1];
}

// ===========================================================================
// Kernel 4: output writer (unchanged).
// ===========================================================================
__global__ void __launch_bounds__(256)
k_write(float* __restrict__ out)
{
    __shared__ unsigned int wcnt[8];
    const int c   = blockIdx.x;
    const int b   = blockIdx.y;
    const int tid = threadIdx.x;

    float* o = out + ((size_t)(b * NCLS + c)) * TOPM * 5;
    for (int i = tid; i < TOPM * 5; i += 256) o[i] = 0.f;
    if (c == 0) return;
    __syncthreads();

    const int c80 = c - 1;
    const size_t base = ((size_t)b * NC + c80) * TOPM;
    const unsigned long long cut = g_cutoff[b];

    float v = 0.f; bool flag = false; float4 bx = make_float4(0.f, 0.f, 0.f, 0.f);
    if (tid < TOPM) {
        v = g_kept[base + tid];
        if (v > 0.f) {
            unsigned long long comp =
                ((unsigned long long)__float_as_uint(v) << 32) |
                (unsigned long long)(0xFFFFFFFFu - (unsigned int)(c80 * TOPM + tid));
            flag = (comp >= cut);
        }
        if (flag) bx = g_cand[base + tid];
    }
    unsigned int ball = __ballot_sync(0xFFFFFFFFu, flag);
    const int wid = tid >> 5, lane = tid & 31;
    if (lane == 0) wcnt[wid] = __popc(ball);
    __syncthreads();
    int off = 0;
    for (int w = 0; w < wid; w++) off += (int)wcnt[w];
    if (flag) {
        int pos = off + __popc(ball & ((1u << lane) - 1));
        float* p = o + (size_t)pos * 5;
        p[0] = v; p[1] = bx.x; p[2] = bx.y; p[3] = bx.z; p[4] = bx.w;
    }
}

// ===========================================================================
extern "C" void kernel_launch(void* const* d_in, const int* in_sizes, int n_in,
                              void* d_out, int out_size)
{
    const float* loc  = (const float*)d_in[0];
    const float* conf = (const float*)d_in[1];
    const float* dbox = (const float*)d_in[2];
    float* out = (float*)d_out;

    k_softmax_decode<<<BATCH * (NANCH / ROWS), 256>>>(loc, conf, dbox);
    k_topk_nms<<<BATCH * NC, 256>>>();
    k_global_cutoff<<<BATCH, 256>>>();
    k_write<<<dim3(NCLS, BATCH), 256>>>(out);
}

// round 16
// speedup vs baseline: 1.6098x; 1.0078x over previous
#include <cuda_runtime.h>
#include <cstdint>

#define BATCH 8
#define NANCH 32768
#define NCLS  81
#define NC    80
#define TOPM  200
#define NMS_TH  0.45f
#define CONF_TH 0.01f
#define NCHUNK  7
#define NBIN    2048
#define ROWS    64
#define NBLK    512      // k1 blocks per batch (NANCH/ROWS)
#define SPEC_BITS 0x3D8F5C29u   // __float_as_uint(0.07f)

__device__ float  g_scores[(size_t)BATCH * NC * NANCH];
__device__ unsigned long long g_mask[(size_t)BATCH * NC * NBLK]; // candidate bitmasks
__device__ float4 g_boxes [(size_t)BATCH * NANCH];
__device__ float  g_kept  [(size_t)BATCH * NC * TOPM];
__device__ float4 g_cand  [(size_t)BATCH * NC * TOPM];
__device__ unsigned long long g_cutoff[BATCH];

__device__ __forceinline__ int score_bin(float v) {
    int b = (int)(__float_as_uint(v) >> 15) - 30720;
    return min(max(b, 0), NBIN - 1);
}

// ===========================================================================
// Kernel 1: NO-MAX softmax + box decode + spec-candidate bitmask emission.
// 64-row blocks, 4 threads/row softmax, 16 threads/class write phase.
// ===========================================================================
__global__ void __launch_bounds__(256)
k_softmax_decode(const float* __restrict__ loc,
                 const float* __restrict__ conf,
                 const float* __restrict__ dbox)
{
    __shared__ float sm[ROWS * NCLS];    // 20736 B
    __shared__ float sinv[ROWS];

    const int blk  = blockIdx.x;
    const int b    = blk / NBLK;
    const int blkb = blk % NBLK;
    const int n0   = blkb * ROWS;
    const int tid  = threadIdx.x;
    const int lane = tid & 31;

    const float4* src4 = reinterpret_cast<const float4*>(
        conf + ((size_t)b * NANCH + n0) * NCLS);
    float4* sm4 = reinterpret_cast<float4*>(sm);
    #pragma unroll
    for (int it = 0; it < 6; it++) {
        int i = tid + it * 256;
        if (i < (ROWS * NCLS) / 4) sm4[i] = src4[i];
    }

    // box decode — threads 0..63
    if (tid < ROWS) {
        const int n = n0 + tid;
        float4 l = reinterpret_cast<const float4*>(loc)[(size_t)b * NANCH + n];
        float4 d = reinterpret_cast<const float4*>(dbox)[n];
        float cx = d.x + l.x * 0.1f * d.z;
        float cy = d.y + l.y * 0.1f * d.w;
        float w  = d.z * expf(l.z * 0.2f);
        float h  = d.w * expf(l.w * 0.2f);
        float x1 = cx - w * 0.5f;
        float y1 = cy - h * 0.5f;
        float4 o;
        o.x = fminf(fmaxf(x1, 0.f), 1.f);
        o.y = fminf(fmaxf(y1, 0.f), 1.f);
        o.z = fminf(fmaxf(x1 + w, 0.f), 1.f);
        o.w = fminf(fmaxf(y1 + h, 0.f), 1.f);
        g_boxes[(size_t)b * NANCH + n] = o;
    }
    __syncthreads();

    // no-max softmax: 4 threads/row; quarters 21/20/20/20 classes
    {
        const int r = tid >> 2;
        const int q = tid & 3;
        const int c0 = (q == 0) ? 0 : (1 + q * 20);
        const int cn = (q == 0) ? 21 : 20;
        float* row = sm + r * NCLS;

        const float L2E = 1.44269504088896340736f;
        float s = 0.f;
        #pragma unroll 7
        for (int c = 0; c < cn; c++) {
            float e = exp2f(row[c0 + c] * L2E);
            row[c0 + c] = e;
            s += e;
        }
        s += __shfl_xor_sync(0xFFFFFFFFu, s, 1);
        s += __shfl_xor_sync(0xFFFFFFFFu, s, 2);
        if (q == 0) sinv[r] = 1.0f / s;
    }
    __syncthreads();

    // write phase: 16 threads/class; dense masked scores + 64-bit spec mask
    #pragma unroll
    for (int it = 0; it < 5; it++) {
        int i = tid + it * 256;                  // i < 16*NC = 1280
        const int c   = i >> 4;                  // 0..79 (class c+1)
        const int rr4 = (i & 15) * 4;
        float4 p;
        float i0 = sinv[rr4], i1 = sinv[rr4+1], i2 = sinv[rr4+2], i3 = sinv[rr4+3];
        p.x = sm[(rr4    ) * NCLS + (c + 1)] * i0;
        p.y = sm[(rr4 + 1) * NCLS + (c + 1)] * i1;
        p.z = sm[(rr4 + 2) * NCLS + (c + 1)] * i2;
        p.w = sm[(rr4 + 3) * NCLS + (c + 1)] * i3;
        p.x = (p.x > CONF_TH) ? p.x : 0.f;
        p.y = (p.y > CONF_TH) ? p.y : 0.f;
        p.z = (p.z > CONF_TH) ? p.z : 0.f;
        p.w = (p.w > CONF_TH) ? p.w : 0.f;
        reinterpret_cast<float4*>(
            g_scores + ((size_t)b * NC + c) * NANCH + n0)[i & 15] = p;

        // spec-candidate nibble for rows rr4..rr4+3
        unsigned int nib =
            ((__float_as_uint(p.x) >= SPEC_BITS) ? 1u : 0u) |
            ((__float_as_uint(p.y) >= SPEC_BITS) ? 2u : 0u) |
            ((__float_as_uint(p.z) >= SPEC_BITS) ? 4u : 0u) |
            ((__float_as_uint(p.w) >= SPEC_BITS) ? 8u : 0u);
        unsigned long long m = (unsigned long long)nib << (4 * (lane & 15));
        m |= __shfl_xor_sync(0xFFFFFFFFu, m, 1);
        m |= __shfl_xor_sync(0xFFFFFFFFu, m, 2);
        m |= __shfl_xor_sync(0xFFFFFFFFu, m, 4);
        m |= __shfl_xor_sync(0xFFFFFFFFu, m, 8);
        if ((lane & 15) == 0)
            g_mask[((size_t)b * NC + c) * NBLK + blkb] = m;
    }
}

// ===========================================================================
// Kernel 2: mask-driven speculative gather (+ exact dense fallback);
// dynamic bitonic + bit-matrix NMS.
// ===========================================================================
__global__ void __launch_bounds__(256)
k_topk_nms()
{
    __shared__ unsigned int hist[NBIN];
    __shared__ unsigned int psum[256];
    __shared__ unsigned long long buf[2048];
    __shared__ unsigned int s_cnt;
    __shared__ int s_bin, s_g, s_P;
    __shared__ float4 s_bx[TOPM];
    __shared__ float  s_area[TOPM];
    __shared__ float  s_sc[TOPM];
    __shared__ unsigned int s_sup[TOPM * NCHUNK];
    __shared__ unsigned int s_act[NCHUNK];
    __shared__ int s_keep[TOPM];

    const int bc  = blockIdx.x;
    const int b   = bc / NC;
    const int tid = threadIdx.x;
    const float* data = g_scores + (size_t)bc * NANCH;
    const float4* d4 = reinterpret_cast<const float4*>(data);
    const unsigned long long* mk = g_mask + (size_t)bc * NBLK;

    if (tid == 0) s_cnt = 0;
    __syncthreads();

    // ---- mask-driven spec gather: ~420 scattered L2-hit loads ----
    for (int blk = tid; blk < NBLK; blk += 256) {
        unsigned long long m = mk[blk];
        while (m) {
            int r = __ffsll(m) - 1;
            m &= m - 1;
            unsigned int idx = blk * ROWS + r;
            unsigned int u = __float_as_uint(data[idx]);
            unsigned int pos = atomicAdd(&s_cnt, 1u);
            if (pos < 2048)
                buf[pos] = ((unsigned long long)u << 32) |
                           (unsigned long long)(0xFFFFFFFFu - idx);
        }
    }
    __syncthreads();
    int cnt = (int)s_cnt;
    __syncthreads();

    // ---- fallback (rare): exact dense hist select + regather ----
    if (cnt < TOPM || cnt > 2048) {
        for (int i = tid; i < NBIN; i += 256) hist[i] = 0;
        if (tid == 0) s_cnt = 0;
        __syncthreads();
        for (int i = tid; i < NANCH / 4; i += 256) {
            float4 v = d4[i];
            if (v.x > CONF_TH) atomicAdd(&hist[score_bin(v.x)], 1u);
            if (v.y > CONF_TH) atomicAdd(&hist[score_bin(v.y)], 1u);
            if (v.z > CONF_TH) atomicAdd(&hist[score_bin(v.z)], 1u);
            if (v.w > CONF_TH) atomicAdd(&hist[score_bin(v.w)], 1u);
        }
        __syncthreads();
        { unsigned int s = 0;
          #pragma unroll
          for (int j = 0; j < 8; j++) s += hist[tid * 8 + j];
          psum[tid] = s; }
        __syncthreads();
        if (tid == 0) {
            int acc = 0, binq = -1;
            for (int t = 255; t >= 0; t--) {
                if (acc + (int)psum[t] >= TOPM) {
                    for (int bb = t * 8 + 7; bb >= t * 8; bb--) {
                        int c2 = (int)hist[bb];
                        if (acc + c2 >= TOPM) { binq = bb; break; }
                        acc += c2;
                    }
                    break;
                }
                acc += (int)psum[t];
            }
            s_bin = binq;
        }
        __syncthreads();
        const int binq = s_bin;
        const unsigned int thr = (binq < 0) ? 0u
                               : ((unsigned int)(binq + 30720) << 15);
        for (int i = tid; i < NANCH / 4; i += 256) {
            float4 v = d4[i];
            const float vs[4] = {v.x, v.y, v.z, v.w};
            #pragma unroll
            for (int j = 0; j < 4; j++) {
                float val = vs[j];
                unsigned int u = __float_as_uint(val);
                if (val > 0.f && u >= thr) {
                    unsigned int pos = atomicAdd(&s_cnt, 1u);
                    if (pos < 2048) {
                        unsigned int idx = 4 * i + j;
                        buf[pos] = ((unsigned long long)u << 32) |
                                   (unsigned long long)(0xFFFFFFFFu - idx);
                    }
                }
            }
        }
        __syncthreads();
        cnt = (int)s_cnt;
        __syncthreads();
    }

    if (tid == 0) {
        int g = min(cnt, 2048);
        int P = 256;
        while (P < g) P <<= 1;
        s_g = g; s_P = P;
    }
    __syncthreads();
    const int g = s_g, P = s_P;
    for (int i = tid; i < P; i += 256) if (i >= g) buf[i] = 0ull;
    __syncthreads();

    for (int k = 2; k <= P; k <<= 1) {
        for (int j = k >> 1; j > 0; j >>= 1) {
            for (int t = tid; t < P; t += 256) {
                int ixj = t ^ j;
                if (ixj > t) {
                    unsigned long long a = buf[t], c2 = buf[ixj];
                    bool dirDesc = ((t & k) == 0);
                    if ((a < c2) == dirDesc) { buf[t] = c2; buf[ixj] = a; }
                }
            }
            __syncthreads();
        }
    }

    bool val_f = false;
    if (tid < TOPM) {
        float sc; float4 bx;
        if (tid < g) {
            unsigned long long cmp = buf[tid];
            sc = __uint_as_float((unsigned int)(cmp >> 32));
            unsigned int idx = 0xFFFFFFFFu - (unsigned int)(cmp & 0xFFFFFFFFull);
            bx = g_boxes[(size_t)b * NANCH + idx];
            val_f = true;
        } else {
            sc = 0.f; bx = make_float4(0.f, 0.f, 0.f, 0.f);
        }
        s_sc[tid]   = sc;
        s_bx[tid]   = bx;
        s_area[tid] = (bx.z - bx.x) * (bx.w - bx.y);
        s_keep[tid] = 0;
    }
    {
        unsigned int bm = __ballot_sync(0xFFFFFFFFu, val_f);
        if ((tid & 31) == 0 && (tid >> 5) < NCHUNK) s_act[tid >> 5] = bm;
    }
    __syncthreads();

    for (int task = tid; task < TOPM * NCHUNK; task += 256) {
        const int i     = task / NCHUNK;
        const int chunk = task % NCHUNK;
        const float4 bi = s_bx[i];
        const float  ai = s_area[i];
        unsigned int bits = 0;
        const int jmax = min(32, TOPM - chunk * 32);
        #pragma unroll 4
        for (int bb = 0; bb < jmax; bb++) {
            const int j = chunk * 32 + bb;
            float4 bj = s_bx[j];
            float xx1 = fmaxf(bi.x, bj.x);
            float yy1 = fmaxf(bi.y, bj.y);
            float xx2 = fminf(bi.z, bj.z);
            float yy2 = fminf(bi.w, bj.w);
            float inter = fmaxf(xx2 - xx1, 0.f) * fmaxf(yy2 - yy1, 0.f);
            float uni   = s_area[j] - inter + ai;
            float iou   = inter / uni;
            if (!(iou <= NMS_TH)) bits |= (1u << bb);
        }
        s_sup[task] = bits;
    }
    __syncthreads();

    if (tid < 32) {
        unsigned int act = (tid < NCHUNK) ? s_act[tid] : 0u;
        for (int i = 0; i < TOPM; i++) {
            unsigned int owner_act = __shfl_sync(0xFFFFFFFFu, act, i >> 5);
            bool k = (owner_act >> (i & 31)) & 1u;
            if (k) {
                if (tid < NCHUNK) act &= ~s_sup[i * NCHUNK + tid];
                if (tid == 0) s_keep[i] = 1;
            }
        }
    }
    __syncthreads();

    if (tid < TOPM) {
        g_kept[(size_t)bc * TOPM + tid] = s_keep[tid] ? s_sc[tid] : 0.f;
        g_cand[(size_t)bc * TOPM + tid] = s_bx[tid];
    }
}

// ===========================================================================
// Kernel 3: per-batch global top-200 composite cutoff (unchanged).
// ===========================================================================
__global__ void __launch_bounds__(256)
k_global_cutoff()
{
    __shared__ unsigned int hist[NBIN];
    __shared__ unsigned int psum[256];
    __shared__ unsigned long long buf[2048];
    __shared__ unsigned int s_cnt;
    __shared__ int s_bin, s_g, s_P;

    const int b   = blockIdx.x;
    const int tid = threadIdx.x;
    const int NTOT = NC * TOPM;
    const float* data = g_kept + (size_t)b * NTOT;
    const float4* d4  = reinterpret_cast<const float4*>(data);

    for (int i = tid; i < NBIN; i += 256) hist[i] = 0;
    __syncthreads();
    for (int i = tid; i < NTOT / 4; i += 256) {
        float4 v = d4[i];
        if (v.x > 0.f) atomicAdd(&hist[score_bin(v.x)], 1u);
        if (v.y > 0.f) atomicAdd(&hist[score_bin(v.y)], 1u);
        if (v.z > 0.f) atomicAdd(&hist[score_bin(v.z)], 1u);
        if (v.w > 0.f) atomicAdd(&hist[score_bin(v.w)], 1u);
    }
    __syncthreads();
    { unsigned int s = 0;
      #pragma unroll
      for (int j = 0; j < 8; j++) s += hist[tid * 8 + j];
      psum[tid] = s; }
    __syncthreads();
    if (tid == 0) {
        int acc = 0, binq = -1;
        for (int t = 255; t >= 0; t--) {
            if (acc + (int)psum[t] >= TOPM) {
                for (int bb = t * 8 + 7; bb >= t * 8; bb--) {
                    int cnt = (int)hist[bb];
                    if (acc + cnt >= TOPM) { binq = bb; break; }
                    acc += cnt;
                }
                break;
            }
            acc += (int)psum[t];
        }
        s_bin = binq;
        s_cnt = 0;
    }
    __syncthreads();
    const int binq = s_bin;

    if (binq < 0) {
        if (tid == 0) g_cutoff[b] = 0ull;
        return;
    }
    const unsigned int thr = (unsigned int)(binq + 30720) << 15;

    for (int i = tid; i < NTOT / 4; i += 256) {
        float4 v = d4[i];
        const float vs[4] = {v.x, v.y, v.z, v.w};
        #pragma unroll
        for (int j = 0; j < 4; j++) {
            float val = vs[j];
            unsigned int u = __float_as_uint(val);
            if (val > 0.f && u >= thr) {
                unsigned int p = atomicAdd(&s_cnt, 1u);
                if (p < 2048) {
                    unsigned int idx = 4 * i + j;
                    buf[p] = ((unsigned long long)u << 32) |
                             (unsigned long long)(0xFFFFFFFFu - idx);
                }
            }
        }
    }
    __syncthreads();
    if (tid == 0) {
        int g = (int)min(s_cnt, 2048u);
        int P = 256;
        while (P < g) P <<= 1;
        s_g = g; s_P = P;
    }
    __syncthreads();
    const int g = s_g, P = s_P;
    for (int i = tid; i < P; i += 256) if (i >= g) buf[i] = 0ull;
    __syncthreads();

    for (int k = 2; k <= P; k <<= 1) {
        for (int j = k >> 1; j > 0; j >>= 1) {
            for (int t = tid; t < P; t += 256) {
                int ixj = t ^ j;
                if (ixj > t) {
                    unsigned long long a = buf[t], c2 = buf[ixj];
                    bool dirDesc = ((t & k) == 0);
                    if ((a < c2) == dirDesc) { buf[t] = c2; buf[ixj] = a; }
                }
            }
            __syncthreads();
        }
    }

    if (tid == 0)
        g_cutoff[b] = buf[TOPM - 1];
}

// ===========================================================================
// Kernel 4: output writer (unchanged).
// ===========================================================================
__global__ void __launch_bounds__(256)
k_write(float* __restrict__ out)
{
    __shared__ unsigned int wcnt[8];
    const int c   = blockIdx.x;
    const int b   = blockIdx.y;
    const int tid = threadIdx.x;

    float* o = out + ((size_t)(b * NCLS + c)) * TOPM * 5;
    for (int i = tid; i < TOPM * 5; i += 256) o[i] = 0.f;
    if (c == 0) return;
    __syncthreads();

    const int c80 = c - 1;
    const size_t base = ((size_t)b * NC + c80) * TOPM;
    const unsigned long long cut = g_cutoff[b];

    float v = 0.f; bool flag = false; float4 bx = make_float4(0.f, 0.f, 0.f, 0.f);
    if (tid < TOPM) {
        v = g_kept[base + tid];
        if (v > 0.f) {
            unsigned long long comp =
                ((unsigned long long)__float_as_uint(v) << 32) |
                (unsigned long long)(0xFFFFFFFFu - (unsigned int)(c80 * TOPM + tid));
            flag = (comp >= cut);
        }
        if (flag) bx = g_cand[base + tid];
    }
    unsigned int ball = __ballot_sync(0xFFFFFFFFu, flag);
    const int wid = tid >> 5, lane = tid & 31;
    if (lane == 0) wcnt[wid] = __popc(ball);
    __syncthreads();
    int off = 0;
    for (int w = 0; w < wid; w++) off += (int)wcnt[w];
    if (flag) {
        int pos = off + __popc(ball & ((1u << lane) - 1));
        float* p = o + (size_t)pos * 5;
        p[0] = v; p[1] = bx.x; p[2] = bx.y; p[3] = bx.z; p[4] = bx.w;
    }
}

// ===========================================================================
extern "C" void kernel_launch(void* const* d_in, const int* in_sizes, int n_in,
                              void* d_out, int out_size)
{
    const float* loc  = (const float*)d_in[0];
    const float* conf = (const float*)d_in[1];
    const float* dbox = (const float*)d_in[2];
    float* out = (float*)d_out;

    k_softmax_decode<<<BATCH * NBLK, 256>>>(loc, conf, dbox);
    k_topk_nms<<<BATCH * NC, 256>>>();
    k_global_cutoff<<<BATCH, 256>>>();
    k_write<<<dim3(NCLS, BATCH), 256>>>(out);
}

// round 17
// speedup vs baseline: 1.6423x; 1.0202x over previous
#include <cuda_runtime.h>
#include <cstdint>

#define BATCH 8
#define NANCH 32768
#define NCLS  81
#define NC    80
#define TOPM  200
#define NMS_TH  0.45f
#define CONF_TH 0.01f
#define NCHUNK  7
#define NBIN    2048
#define ROWS    64
#define NBLK    512      // k1 blocks per batch (NANCH/ROWS)
#define SPEC_BITS 0x3D8F5C29u   // __float_as_uint(0.07f)
#define L2E 1.44269504088896340736f

__device__ unsigned long long g_mask[(size_t)BATCH * NC * NBLK]; // candidate bitmasks
__device__ float  g_sinv [(size_t)BATCH * NANCH];                // 1/rowsum
__device__ float4 g_boxes[(size_t)BATCH * NANCH];
__device__ float  g_kept [(size_t)BATCH * NC * TOPM];
__device__ float4 g_cand [(size_t)BATCH * NC * TOPM];
__device__ unsigned long long g_cutoff[BATCH];

__device__ __forceinline__ int score_bin(float v) {
    int b = (int)(__float_as_uint(v) >> 15) - 30720;
    return min(max(b, 0), NBIN - 1);
}

// ===========================================================================
// Kernel 1: NO-MAX softmax + box decode; emits ONLY masks + sinv + boxes.
// ===========================================================================
__global__ void __launch_bounds__(256)
k_softmax_decode(const float* __restrict__ loc,
                 const float* __restrict__ conf,
                 const float* __restrict__ dbox)
{
    __shared__ float sm[ROWS * NCLS];    // 20736 B
    __shared__ float sinv[ROWS];

    const int blk  = blockIdx.x;
    const int b    = blk / NBLK;
    const int blkb = blk % NBLK;
    const int n0   = blkb * ROWS;
    const int tid  = threadIdx.x;
    const int lane = tid & 31;

    const float4* src4 = reinterpret_cast<const float4*>(
        conf + ((size_t)b * NANCH + n0) * NCLS);
    float4* sm4 = reinterpret_cast<float4*>(sm);
    #pragma unroll
    for (int it = 0; it < 6; it++) {
        int i = tid + it * 256;
        if (i < (ROWS * NCLS) / 4) sm4[i] = src4[i];
    }

    // box decode — threads 0..63
    if (tid < ROWS) {
        const int n = n0 + tid;
        float4 l = reinterpret_cast<const float4*>(loc)[(size_t)b * NANCH + n];
        float4 d = reinterpret_cast<const float4*>(dbox)[n];
        float cx = d.x + l.x * 0.1f * d.z;
        float cy = d.y + l.y * 0.1f * d.w;
        float w  = d.z * expf(l.z * 0.2f);
        float h  = d.w * expf(l.w * 0.2f);
        float x1 = cx - w * 0.5f;
        float y1 = cy - h * 0.5f;
        float4 o;
        o.x = fminf(fmaxf(x1, 0.f), 1.f);
        o.y = fminf(fmaxf(y1, 0.f), 1.f);
        o.z = fminf(fmaxf(x1 + w, 0.f), 1.f);
        o.w = fminf(fmaxf(y1 + h, 0.f), 1.f);
        g_boxes[(size_t)b * NANCH + n] = o;
    }
    __syncthreads();

    // no-max softmax sums: 4 threads/row; quarters 21/20/20/20
    {
        const int r = tid >> 2;
        const int q = tid & 3;
        const int c0 = (q == 0) ? 0 : (1 + q * 20);
        const int cn = (q == 0) ? 21 : 20;
        float* row = sm + r * NCLS;

        float s = 0.f;
        #pragma unroll 7
        for (int c = 0; c < cn; c++) {
            float e = exp2f(row[c0 + c] * L2E);
            row[c0 + c] = e;
            s += e;
        }
        s += __shfl_xor_sync(0xFFFFFFFFu, s, 1);
        s += __shfl_xor_sync(0xFFFFFFFFu, s, 2);
        if (q == 0) {
            float iv = 1.0f / s;
            sinv[r] = iv;
            g_sinv[(size_t)b * NANCH + n0 + r] = iv;
        }
    }
    __syncthreads();

    // mask emission only: 16 threads/class build a 64-bit candidate mask
    #pragma unroll
    for (int it = 0; it < 5; it++) {
        int i = tid + it * 256;                  // i < 16*NC = 1280
        const int c   = i >> 4;                  // 0..79 (class c+1)
        const int rr4 = (i & 15) * 4;
        float p0 = sm[(rr4    ) * NCLS + (c + 1)] * sinv[rr4];
        float p1 = sm[(rr4 + 1) * NCLS + (c + 1)] * sinv[rr4 + 1];
        float p2 = sm[(rr4 + 2) * NCLS + (c + 1)] * sinv[rr4 + 2];
        float p3 = sm[(rr4 + 3) * NCLS + (c + 1)] * sinv[rr4 + 3];
        unsigned int nib =
            ((__float_as_uint(p0) >= SPEC_BITS) ? 1u : 0u) |
            ((__float_as_uint(p1) >= SPEC_BITS) ? 2u : 0u) |
            ((__float_as_uint(p2) >= SPEC_BITS) ? 4u : 0u) |
            ((__float_as_uint(p3) >= SPEC_BITS) ? 8u : 0u);
        unsigned long long m = (unsigned long long)nib << (4 * (lane & 15));
        m |= __shfl_xor_sync(0xFFFFFFFFu, m, 1);
        m |= __shfl_xor_sync(0xFFFFFFFFu, m, 2);
        m |= __shfl_xor_sync(0xFFFFFFFFu, m, 4);
        m |= __shfl_xor_sync(0xFFFFFFFFu, m, 8);
        if ((lane & 15) == 0)
            g_mask[((size_t)b * NC + c) * NBLK + blkb] = m;
    }
}

// ===========================================================================
// Kernel 2: mask-driven gather with on-demand recompute (bit-identical to
// k1's predicate math); exact recompute fallback; bitonic + NMS.
// ===========================================================================
__global__ void __launch_bounds__(256)
k_topk_nms(const float* __restrict__ conf)
{
    __shared__ unsigned int hist[NBIN];
    __shared__ unsigned int psum[256];
    __shared__ unsigned long long buf[2048];
    __shared__ unsigned int s_cnt;
    __shared__ int s_bin, s_g, s_P;
    __shared__ float4 s_bx[TOPM];
    __shared__ float  s_area[TOPM];
    __shared__ float  s_sc[TOPM];
    __shared__ unsigned int s_sup[TOPM * NCHUNK];
    __shared__ unsigned int s_act[NCHUNK];
    __shared__ int s_keep[TOPM];

    const int bc  = blockIdx.x;
    const int b   = bc / NC;
    const int c1  = bc % NC + 1;            // class column in conf
    const int tid = threadIdx.x;
    const unsigned long long* mk = g_mask + (size_t)bc * NBLK;
    const float* cf = conf + (size_t)b * NANCH * NCLS;
    const float* sv = g_sinv + (size_t)b * NANCH;

    if (tid == 0) s_cnt = 0;
    __syncthreads();

    // ---- mask-driven gather: recompute p exactly as k1 did ----
    for (int blk = tid; blk < NBLK; blk += 256) {
        unsigned long long m = mk[blk];
        while (m) {
            int r = __ffsll(m) - 1;
            m &= m - 1;
            unsigned int idx = blk * ROWS + r;
            float p = exp2f(cf[(size_t)idx * NCLS + c1] * L2E) * sv[idx];
            unsigned int pos = atomicAdd(&s_cnt, 1u);
            if (pos < 2048)
                buf[pos] = ((unsigned long long)__float_as_uint(p) << 32) |
                           (unsigned long long)(0xFFFFFFFFu - idx);
        }
    }
    __syncthreads();
    int cnt = (int)s_cnt;
    __syncthreads();

    // ---- fallback (rare): exact full-column recompute, hist + regather ----
    if (cnt < TOPM || cnt > 2048) {
        for (int i = tid; i < NBIN; i += 256) hist[i] = 0;
        if (tid == 0) s_cnt = 0;
        __syncthreads();
        for (int i = tid; i < NANCH; i += 256) {
            float p = exp2f(cf[(size_t)i * NCLS + c1] * L2E) * sv[i];
            if (p > CONF_TH) atomicAdd(&hist[score_bin(p)], 1u);
        }
        __syncthreads();
        { unsigned int s = 0;
          #pragma unroll
          for (int j = 0; j < 8; j++) s += hist[tid * 8 + j];
          psum[tid] = s; }
        __syncthreads();
        if (tid == 0) {
            int acc = 0, binq = -1;
            for (int t = 255; t >= 0; t--) {
                if (acc + (int)psum[t] >= TOPM) {
                    for (int bb = t * 8 + 7; bb >= t * 8; bb--) {
                        int c2 = (int)hist[bb];
                        if (acc + c2 >= TOPM) { binq = bb; break; }
                        acc += c2;
                    }
                    break;
                }
                acc += (int)psum[t];
            }
            s_bin = binq;
        }
        __syncthreads();
        const int binq = s_bin;
        const unsigned int thr = (binq < 0) ? 0u
                               : ((unsigned int)(binq + 30720) << 15);
        for (int i = tid; i < NANCH; i += 256) {
            float p = exp2f(cf[(size_t)i * NCLS + c1] * L2E) * sv[i];
            unsigned int u = __float_as_uint(p);
            if (p > CONF_TH && u >= thr) {
                unsigned int pos = atomicAdd(&s_cnt, 1u);
                if (pos < 2048)
                    buf[pos] = ((unsigned long long)u << 32) |
                               (unsigned long long)(0xFFFFFFFFu - (unsigned int)i);
            }
        }
        __syncthreads();
        cnt = (int)s_cnt;
        __syncthreads();
    }

    if (tid == 0) {
        int g = min(cnt, 2048);
        int P = 256;
        while (P < g) P <<= 1;
        s_g = g; s_P = P;
    }
    __syncthreads();
    const int g = s_g, P = s_P;
    for (int i = tid; i < P; i += 256) if (i >= g) buf[i] = 0ull;
    __syncthreads();

    for (int k = 2; k <= P; k <<= 1) {
        for (int j = k >> 1; j > 0; j >>= 1) {
            for (int t = tid; t < P; t += 256) {
                int ixj = t ^ j;
                if (ixj > t) {
                    unsigned long long a = buf[t], c2 = buf[ixj];
                    bool dirDesc = ((t & k) == 0);
                    if ((a < c2) == dirDesc) { buf[t] = c2; buf[ixj] = a; }
                }
            }
            __syncthreads();
        }
    }

    bool val_f = false;
    if (tid < TOPM) {
        float sc; float4 bx;
        if (tid < g) {
            unsigned long long cmp = buf[tid];
            sc = __uint_as_float((unsigned int)(cmp >> 32));
            unsigned int idx = 0xFFFFFFFFu - (unsigned int)(cmp & 0xFFFFFFFFull);
            bx = g_boxes[(size_t)b * NANCH + idx];
            val_f = true;
        } else {
            sc = 0.f; bx = make_float4(0.f, 0.f, 0.f, 0.f);
        }
        s_sc[tid]   = sc;
        s_bx[tid]   = bx;
        s_area[tid] = (bx.z - bx.x) * (bx.w - bx.y);
        s_keep[tid] = 0;
    }
    {
        unsigned int bm = __ballot_sync(0xFFFFFFFFu, val_f);
        if ((tid & 31) == 0 && (tid >> 5) < NCHUNK) s_act[tid >> 5] = bm;
    }
    __syncthreads();

    for (int task = tid; task < TOPM * NCHUNK; task += 256) {
        const int i     = task / NCHUNK;
        const int chunk = task % NCHUNK;
        const float4 bi = s_bx[i];
        const float  ai = s_area[i];
        unsigned int bits = 0;
        const int jmax = min(32, TOPM - chunk * 32);
        #pragma unroll 4
        for (int bb = 0; bb < jmax; bb++) {
            const int j = chunk * 32 + bb;
            float4 bj = s_bx[j];
            float xx1 = fmaxf(bi.x, bj.x);
            float yy1 = fmaxf(bi.y, bj.y);
            float xx2 = fminf(bi.z, bj.z);
            float yy2 = fminf(bi.w, bj.w);
            float inter = fmaxf(xx2 - xx1, 0.f) * fmaxf(yy2 - yy1, 0.f);
            float uni   = s_area[j] - inter + ai;
            float iou   = inter / uni;
            if (!(iou <= NMS_TH)) bits |= (1u << bb);
        }
        s_sup[task] = bits;
    }
    __syncthreads();

    if (tid < 32) {
        unsigned int act = (tid < NCHUNK) ? s_act[tid] : 0u;
        for (int i = 0; i < TOPM; i++) {
            unsigned int owner_act = __shfl_sync(0xFFFFFFFFu, act, i >> 5);
            bool k = (owner_act >> (i & 31)) & 1u;
            if (k) {
                if (tid < NCHUNK) act &= ~s_sup[i * NCHUNK + tid];
                if (tid == 0) s_keep[i] = 1;
            }
        }
    }
    __syncthreads();

    if (tid < TOPM) {
        g_kept[(size_t)bc * TOPM + tid] = s_keep[tid] ? s_sc[tid] : 0.f;
        g_cand[(size_t)bc * TOPM + tid] = s_bx[tid];
    }
}

// ===========================================================================
// Kernel 3: per-batch global top-200 composite cutoff (unchanged).
// ===========================================================================
__global__ void __launch_bounds__(256)
k_global_cutoff()
{
    __shared__ unsigned int hist[NBIN];
    __shared__ unsigned int psum[256];
    __shared__ unsigned long long buf[2048];
    __shared__ unsigned int s_cnt;
    __shared__ int s_bin, s_g, s_P;

    const int b   = blockIdx.x;
    const int tid = threadIdx.x;
    const int NTOT = NC * TOPM;
    const float* data = g_kept + (size_t)b * NTOT;
    const float4* d4  = reinterpret_cast<const float4*>(data);

    for (int i = tid; i < NBIN; i += 256) hist[i] = 0;
    __syncthreads();
    for (int i = tid; i < NTOT / 4; i += 256) {
        float4 v = d4[i];
        if (v.x > 0.f) atomicAdd(&hist[score_bin(v.x)], 1u);
        if (v.y > 0.f) atomicAdd(&hist[score_bin(v.y)], 1u);
        if (v.z > 0.f) atomicAdd(&hist[score_bin(v.z)], 1u);
        if (v.w > 0.f) atomicAdd(&hist[score_bin(v.w)], 1u);
    }
    __syncthreads();
    { unsigned int s = 0;
      #pragma unroll
      for (int j = 0; j < 8; j++) s += hist[tid * 8 + j];
      psum[tid] = s; }
    __syncthreads();
    if (tid == 0) {
        int acc = 0, binq = -1;
        for (int t = 255; t >= 0; t--) {
            if (acc + (int)psum[t] >= TOPM) {
                for (int bb = t * 8 + 7; bb >= t * 8; bb--) {
                    int cnt = (int)hist[bb];
                    if (acc + cnt >= TOPM) { binq = bb; break; }
                    acc += cnt;
                }
                break;
            }
            acc += (int)psum[t];
        }
        s_bin = binq;
        s_cnt = 0;
    }
    __syncthreads();
    const int binq = s_bin;

    if (binq < 0) {
        if (tid == 0) g_cutoff[b] = 0ull;
        return;
    }
    const unsigned int thr = (unsigned int)(binq + 30720) << 15;

    for (int i = tid; i < NTOT / 4; i += 256) {
        float4 v = d4[i];
        const float vs[4] = {v.x, v.y, v.z, v.w};
        #pragma unroll
        for (int j = 0; j < 4; j++) {
            float val = vs[j];
            unsigned int u = __float_as_uint(val);
            if (val > 0.f && u >= thr) {
                unsigned int p = atomicAdd(&s_cnt, 1u);
                if (p < 2048) {
                    unsigned int idx = 4 * i + j;
                    buf[p] = ((unsigned long long)u << 32) |
                             (unsigned long long)(0xFFFFFFFFu - idx);
                }
            }
        }
    }
    __syncthreads();
    if (tid == 0) {
        int g = (int)min(s_cnt, 2048u);
        int P = 256;
        while (P < g) P <<= 1;
        s_g = g; s_P = P;
    }
    __syncthreads();
    const int g = s_g, P = s_P;
    for (int i = tid; i < P; i += 256) if (i >= g) buf[i] = 0ull;
    __syncthreads();

    for (int k = 2; k <= P; k <<= 1) {
        for (int j = k >> 1; j > 0; j >>= 1) {
            for (int t = tid; t < P; t += 256) {
                int ixj = t ^ j;
                if (ixj > t) {
                    unsigned long long a = buf[t], c2 = buf[ixj];
                    bool dirDesc = ((t & k) == 0);
                    if ((a < c2) == dirDesc) { buf[t] = c2; buf[ixj] = a; }
                }
            }
            __syncthreads();
        }
    }

    if (tid == 0)
        g_cutoff[b] = buf[TOPM - 1];
}

// ===========================================================================
// Kernel 4: output writer (unchanged).
// ===========================================================================
__global__ void __launch_bounds__(256)
k_write(float* __restrict__ out)
{
    __shared__ unsigned int wcnt[8];
    const int c   = blockIdx.x;
    const int b   = blockIdx.y;
    const int tid = threadIdx.x;

    float* o = out + ((size_t)(b * NCLS + c)) * TOPM * 5;
    for (int i = tid; i < TOPM * 5; i += 256) o[i] = 0.f;
    if (c == 0) return;
    __syncthreads();

    const int c80 = c - 1;
    const size_t base = ((size_t)b * NC + c80) * TOPM;
    const unsigned long long cut = g_cutoff[b];

    float v = 0.f; bool flag = false; float4 bx = make_float4(0.f, 0.f, 0.f, 0.f);
    if (tid < TOPM) {
        v = g_kept[base + tid];
        if (v > 0.f) {
            unsigned long long comp =
                ((unsigned long long)__float_as_uint(v) << 32) |
                (unsigned long long)(0xFFFFFFFFu - (unsigned int)(c80 * TOPM + tid));
            flag = (comp >= cut);
        }
        if (flag) bx = g_cand[base + tid];
    }
    unsigned int ball = __ballot_sync(0xFFFFFFFFu, flag);
    const int wid = tid >> 5, lane = tid & 31;
    if (lane == 0) wcnt[wid] = __popc(ball);
    __syncthreads();
    int off = 0;
    for (int w = 0; w < wid; w++) off += (int)wcnt[w];
    if (flag) {
        int pos = off + __popc(ball & ((1u << lane) - 1));
        float* p = o + (size_t)pos * 5;
        p[0] = v; p[1] = bx.x; p[2] = bx.y; p[3] = bx.z; p[4] = bx.w;
    }
}

// ===========================================================================
extern "C" void kernel_launch(void* const* d_in, const int* in_sizes, int n_in,
                              void* d_out, int out_size)
{
    const float* loc  = (const float*)d_in[0];
    const float* conf = (const float*)d_in[1];
    const float* dbox = (const float*)d_in[2];
    float* out = (float*)d_out;

    k_softmax_decode<<<BATCH * NBLK, 256>>>(loc, conf, dbox);
    k_topk_nms<<<BATCH * NC, 256>>>(conf);
    k_global_cutoff<<<BATCH, 256>>>();
    k_write<<<dim3(NCLS, BATCH), 256>>>(out);
}